// round 1
// baseline (speedup 1.0000x reference)
#include <cuda_runtime.h>
#include <cuda_bf16.h>

// DiffAttention: out[n,h,d] = sum_l sigmoid(q[n,h,:]·k[l,h,:]) * v[l,h,d] / sum_l sigmoid(...)
// N=L=4096, H=8, M=D=64. Single fused pass over l (sigmoid normalizer needs no max).
//
// Tiling: each CTA = (BM=128 query rows) x (one head), loops over L in BL=64 chunks.
// smem: Q[128x64] (persistent), K^T[64x64], V[64x64], S[128x64] staging.
// 256 threads, each owns an 8x4 fragment of both the S tile and the output tile.

#define NN 4096
#define LL 4096
#define HH 8
#define MM 64
#define DD 64
#define BM 128
#define BL 64
#define NTHREADS 256

// smem layout (floats): q[BM*MM]=8192, kT[MM*BL]=4096, v[BL*DD]=4096, s[BM*BL]=8192
// total 24576 floats = 96 KB
#define SMEM_FLOATS (BM*MM + MM*BL + BL*DD + BM*BL)

__global__ __launch_bounds__(NTHREADS, 2)
void diff_attention_kernel(const float* __restrict__ queries,
                           const float* __restrict__ keys,
                           const float* __restrict__ values,
                           float* __restrict__ out)
{
    extern __shared__ float smem[];
    float* sq  = smem;                 // [row][m]  row-major, 128x64
    float* skT = sq  + BM * MM;        // [m][l]    transposed K tile, 64x64
    float* sv  = skT + MM * BL;        // [l][d]    row-major, 64x64
    float* ss  = sv  + BL * DD;        // [row][l]  sigmoid scores, 128x64

    const int tid = threadIdx.x;
    const int ty  = tid >> 4;          // 0..15 -> rows ty*8 .. ty*8+7
    const int tx  = tid & 15;          // 0..15 -> cols tx*4 .. tx*4+3

    const int h  = blockIdx.x & (HH - 1);
    const int n0 = (blockIdx.x >> 3) * BM;

    // ---- load Q tile (persistent across the whole kernel) ----
    // q_smem[row][m]; coalesced float4 global reads, conflict-free stores
    for (int c = tid; c < BM * MM / 4; c += NTHREADS) {
        const int row = c >> 4;        // 0..127
        const int m4  = c & 15;        // 0..15
        const float4 t = *(const float4*)(queries +
            ((size_t)(n0 + row) * HH + h) * MM + m4 * 4);
        *(float4*)(sq + row * MM + m4 * 4) = t;
    }

    float acco[8][4];                  // output numerator accumulator (n x d frag)
    float norm[8];                     // per-row normalizer partials (this thread's 4 cols)
    #pragma unroll
    for (int i = 0; i < 8; i++) {
        norm[i] = 0.f;
        #pragma unroll
        for (int j = 0; j < 4; j++) acco[i][j] = 0.f;
    }

    __syncthreads();

    for (int lt = 0; lt < LL / BL; lt++) {
        const int l0 = lt * BL;

        // ---- load K tile transposed: skT[m][l] = K[l0+l, h, m] ----
        // lanes iterate consecutive l for a fixed m4 -> conflict-free STS,
        // (global reads strided by 2KB — cheap, memory is far from the bottleneck)
        for (int c = tid; c < (MM / 4) * BL; c += NTHREADS) {
            const int m4 = c >> 6;     // 0..15
            const int l  = c & 63;     // 0..63
            const float4 t = *(const float4*)(keys +
                ((size_t)(l0 + l) * HH + h) * MM + m4 * 4);
            skT[(m4 * 4 + 0) * BL + l] = t.x;
            skT[(m4 * 4 + 1) * BL + l] = t.y;
            skT[(m4 * 4 + 2) * BL + l] = t.z;
            skT[(m4 * 4 + 3) * BL + l] = t.w;
        }
        // ---- load V tile: sv[l][d] natural layout, fully coalesced ----
        for (int c = tid; c < BL * DD / 4; c += NTHREADS) {
            const int l  = c >> 4;     // 0..63
            const int d4 = c & 15;     // 0..15
            *(float4*)(sv + l * DD + d4 * 4) = *(const float4*)(values +
                ((size_t)(l0 + l) * HH + h) * DD + d4 * 4);
        }
        __syncthreads();

        // ---- GEMM1: S[row][col] = sum_m Q[row][m] * K^T[m][col] ----
        float accs[8][4];
        #pragma unroll
        for (int i = 0; i < 8; i++)
            #pragma unroll
            for (int j = 0; j < 4; j++) accs[i][j] = 0.f;

        #pragma unroll 4
        for (int m4 = 0; m4 < MM / 4; m4++) {
            float4 kf[4];
            #pragma unroll
            for (int s = 0; s < 4; s++)
                kf[s] = *(const float4*)(skT + (m4 * 4 + s) * BL + tx * 4);
            #pragma unroll
            for (int i = 0; i < 8; i++) {
                const float4 qf = *(const float4*)(sq + (ty * 8 + i) * MM + m4 * 4);
                #pragma unroll
                for (int j = 0; j < 4; j++) {
                    float* kj0 = &kf[0].x;  // kf[s] component j
                    // expand manually for clean FFMA chains
                    accs[i][j] = fmaf(qf.x, (&kf[0].x)[j],
                                 fmaf(qf.y, (&kf[1].x)[j],
                                 fmaf(qf.z, (&kf[2].x)[j],
                                 fmaf(qf.w, (&kf[3].x)[j], accs[i][j]))));
                    (void)kj0;
                }
            }
        }

        // ---- sigmoid + normalizer partials + stage S to smem ----
        #pragma unroll
        for (int i = 0; i < 8; i++) {
            #pragma unroll
            for (int j = 0; j < 4; j++) {
                const float sgd = __fdividef(1.f, 1.f + __expf(-accs[i][j]));
                accs[i][j] = sgd;
                norm[i] += sgd;
            }
            *(float4*)(ss + (ty * 8 + i) * BL + tx * 4) =
                make_float4(accs[i][0], accs[i][1], accs[i][2], accs[i][3]);
        }
        __syncthreads();

        // ---- GEMM2: acco[row][d] += sum_l S[row][l] * V[l][d] ----
        #pragma unroll 4
        for (int l4 = 0; l4 < BL / 4; l4++) {
            float4 vf[4];
            #pragma unroll
            for (int s = 0; s < 4; s++)
                vf[s] = *(const float4*)(sv + (l4 * 4 + s) * DD + tx * 4);
            #pragma unroll
            for (int i = 0; i < 8; i++) {
                const float4 sf = *(const float4*)(ss + (ty * 8 + i) * BL + l4 * 4);
                #pragma unroll
                for (int j = 0; j < 4; j++) {
                    acco[i][j] = fmaf(sf.x, (&vf[0].x)[j],
                                 fmaf(sf.y, (&vf[1].x)[j],
                                 fmaf(sf.z, (&vf[2].x)[j],
                                 fmaf(sf.w, (&vf[3].x)[j], acco[i][j]))));
                }
            }
        }
        __syncthreads();   // protect skT/sv/ss before next iteration overwrites
    }

    // ---- reduce normalizer across the 16 tx lanes (same 16-lane shuffle group) ----
    // tid = ty*16 + tx -> lanes [0..15] and [16..31] of a warp are two tx groups.
    float inv[8];
    #pragma unroll
    for (int i = 0; i < 8; i++) {
        float nsum = norm[i];
        #pragma unroll
        for (int off = 8; off > 0; off >>= 1)
            nsum += __shfl_xor_sync(0xffffffffu, nsum, off, 16);
        inv[i] = __fdividef(1.f, nsum);
    }

    // ---- write output: out[(n0+row), h, d], coalesced float4 ----
    #pragma unroll
    for (int i = 0; i < 8; i++) {
        const int row = ty * 8 + i;
        float4 o = make_float4(acco[i][0] * inv[i], acco[i][1] * inv[i],
                               acco[i][2] * inv[i], acco[i][3] * inv[i]);
        *(float4*)(out + ((size_t)(n0 + row) * HH + h) * DD + tx * 4) = o;
    }
}

extern "C" void kernel_launch(void* const* d_in, const int* in_sizes, int n_in,
                              void* d_out, int out_size)
{
    const float* queries = (const float*)d_in[0];
    const float* keys    = (const float*)d_in[1];
    const float* values  = (const float*)d_in[2];
    float* out = (float*)d_out;

    const int smem_bytes = SMEM_FLOATS * sizeof(float);   // 96 KB
    cudaFuncSetAttribute(diff_attention_kernel,
                         cudaFuncAttributeMaxDynamicSharedMemorySize, smem_bytes);

    const dim3 grid((NN / BM) * HH);   // 32 * 8 = 256 CTAs
    diff_attention_kernel<<<grid, NTHREADS, smem_bytes>>>(queries, keys, values, out);
}

// round 4
// speedup vs baseline: 2.7065x; 2.7065x over previous
#include <cuda_runtime.h>
#include <cuda_bf16.h>
#include <cstdint>

// DiffAttention via Ampere-style mma.sync bf16 hi/lo-split (fp32-accurate emulation).
// tcgen05 is unavailable: harness PTX targets compute_103 (no 'a'), so only
// baseline-PTX tensor instructions (mma.sync + ldmatrix) are usable.
//
// out[n,h,d] = sum_l sigmoid(q.k) * v / sum_l sigmoid(q.k);  N=L=4096, H=8, M=D=64.
// CTA = 128 query rows x 1 head; loop over L in BL=64 tiles; 8 warps, each owns
// 16 query rows x full 64 cols. GEMM1 C-frags (S scores) are sigmoid'ed, norm-
// accumulated, and hi/lo-split into GEMM2 A-frags entirely in registers.

#define NN 4096
#define LL 4096
#define HH 8
#define MM 64
#define DD 64
#define BM 128
#define BL 64
#define NTHREADS 256

// smem byte offsets, all rows 128B (64 bf16), SW128-swizzled
#define SQH 0           // Q hi 128x64 bf16 (16KB)
#define SQL 16384       // Q lo
#define SKH 32768       // K hi 64x64 [l][m] (8KB)
#define SKL 40960
#define SVH 49152       // V hi 64x64 [l][d] (8KB)
#define SVL 57344
#define SMEM_BYTES (65536 + 1024)

static __device__ __forceinline__ uint32_t smem_u32(const void* p) {
    uint32_t a;
    asm("{ .reg .u64 t; cvta.to.shared.u64 t, %1; cvt.u32.u64 %0, t; }" : "=r"(a) : "l"(p));
    return a;
}
static __device__ __forceinline__ uint32_t sw128(uint32_t off) {
    return off ^ ((off >> 3) & 0x70);
}

static __device__ __forceinline__ void ldmx4(uint32_t addr, uint32_t r[4]) {
    asm volatile("ldmatrix.sync.aligned.m8n8.x4.shared.b16 {%0,%1,%2,%3}, [%4];"
        : "=r"(r[0]), "=r"(r[1]), "=r"(r[2]), "=r"(r[3]) : "r"(addr));
}
static __device__ __forceinline__ void ldmx4t(uint32_t addr, uint32_t r[4]) {
    asm volatile("ldmatrix.sync.aligned.m8n8.x4.trans.shared.b16 {%0,%1,%2,%3}, [%4];"
        : "=r"(r[0]), "=r"(r[1]), "=r"(r[2]), "=r"(r[3]) : "r"(addr));
}
static __device__ __forceinline__ void mma16816(float d[4], const uint32_t a[4],
                                                uint32_t b0, uint32_t b1) {
    asm volatile(
        "mma.sync.aligned.m16n8k16.row.col.f32.bf16.bf16.f32 "
        "{%0,%1,%2,%3}, {%4,%5,%6,%7}, {%8,%9}, {%0,%1,%2,%3};"
        : "+f"(d[0]), "+f"(d[1]), "+f"(d[2]), "+f"(d[3])
        : "r"(a[0]), "r"(a[1]), "r"(a[2]), "r"(a[3]), "r"(b0), "r"(b1));
}

// split two floats into packed bf16x2 hi + bf16x2 lo (x ~= hi + lo, ~17-bit mantissa)
static __device__ __forceinline__ void split2(float x0, float x1, uint32_t& hi, uint32_t& lo) {
    __nv_bfloat162 h2 = __floats2bfloat162_rn(x0, x1);
    float r0 = x0 - __bfloat162float(h2.x);
    float r1 = x1 - __bfloat162float(h2.y);
    __nv_bfloat162 l2 = __floats2bfloat162_rn(r0, r1);
    hi = *reinterpret_cast<uint32_t*>(&h2);
    lo = *reinterpret_cast<uint32_t*>(&l2);
}
static __device__ __forceinline__ float sigmoidf_fast(float x) {
    return __fdividef(1.0f, 1.0f + __expf(-x));
}

__global__ __launch_bounds__(NTHREADS, 2)
void diffattn_hmma(const float* __restrict__ Q, const float* __restrict__ K,
                   const float* __restrict__ V, float* __restrict__ out)
{
    extern __shared__ char smem_raw[];
    char* sp = (char*)((((uintptr_t)smem_raw) + 1023) & ~(uintptr_t)1023);
    const uint32_t sb = smem_u32(sp);

    const int tid = threadIdx.x;
    const int wid = tid >> 5;
    const int lid = tid & 31;
    const int h  = blockIdx.x & (HH - 1);
    const int n0 = (blockIdx.x >> 3) * BM;
    const int mw = wid * 16;               // this warp's query-row block

    // ---- stage Q tile once: split to bf16 hi/lo, SW128-swizzled [row][m] ----
    for (int c = tid; c < BM * MM / 4; c += NTHREADS) {
        const int row = c >> 4, m4 = c & 15;
        const float4 t = *(const float4*)(Q + ((size_t)(n0 + row) * HH + h) * MM + m4 * 4);
        uint32_t h0, l0r, h1, l1r;
        split2(t.x, t.y, h0, l0r); split2(t.z, t.w, h1, l1r);
        const uint32_t off = sw128(row * 128 + m4 * 8);
        *(uint2*)(sp + SQH + off) = make_uint2(h0, h1);
        *(uint2*)(sp + SQL + off) = make_uint2(l0r, l1r);
    }
    __syncthreads();

    // ---- preload Q A-fragments (persistent): 4 k-steps x (hi,lo) ----
    // A-frag tile order: m0=rows lo/k lo, m1=rows hi/k lo, m2=rows lo/k hi, m3=rows hi/k hi
    uint32_t qh[4][4], ql[4][4];
    {
        const int t4 = lid >> 3, r8 = lid & 7;
        #pragma unroll
        for (int k = 0; k < 4; k++) {
            const int row = mw + (t4 & 1) * 8 + r8;
            const int kc  = k * 16 + (t4 >> 1) * 8;
            const uint32_t off = sw128(row * 128 + kc * 2);
            ldmx4(sb + SQH + off, qh[k]);
            ldmx4(sb + SQL + off, ql[k]);
        }
    }

    float oacc[8][4];                      // output accumulator: 8 n-tiles (d)
    #pragma unroll
    for (int j = 0; j < 8; j++)
        #pragma unroll
        for (int i = 0; i < 4; i++) oacc[j][i] = 0.f;
    float normLo = 0.f, normHi = 0.f;      // rows mw+lid/4 and mw+8+lid/4

    const int t4 = lid >> 3, r8 = lid & 7; // ldmatrix lane decomposition

    for (int lt = 0; lt < LL / BL; lt++) {
        const int l0g = lt * BL;

        // ---- stage K tile [l][m] and V tile [l][d], bf16 hi/lo ----
        #pragma unroll
        for (int c = tid; c < BL * MM / 4; c += NTHREADS) {
            const int row = c >> 4, m4 = c & 15;
            const float4 t = *(const float4*)(K + ((size_t)(l0g + row) * HH + h) * MM + m4 * 4);
            uint32_t h0, l0r, h1, l1r;
            split2(t.x, t.y, h0, l0r); split2(t.z, t.w, h1, l1r);
            const uint32_t off = sw128(row * 128 + m4 * 8);
            *(uint2*)(sp + SKH + off) = make_uint2(h0, h1);
            *(uint2*)(sp + SKL + off) = make_uint2(l0r, l1r);
        }
        #pragma unroll
        for (int c = tid; c < BL * DD / 4; c += NTHREADS) {
            const int row = c >> 4, d4 = c & 15;
            const float4 t = *(const float4*)(V + ((size_t)(l0g + row) * HH + h) * DD + d4 * 4);
            uint32_t h0, l0r, h1, l1r;
            split2(t.x, t.y, h0, l0r); split2(t.z, t.w, h1, l1r);
            const uint32_t off = sw128(row * 128 + d4 * 8);
            *(uint2*)(sp + SVH + off) = make_uint2(h0, h1);
            *(uint2*)(sp + SVL + off) = make_uint2(l0r, l1r);
        }
        __syncthreads();

        // ---- GEMM1: S[16x64] = Q K^T, 3-way split (qh*kh + qh*kl + ql*kh) ----
        float sacc[8][4];
        #pragma unroll
        for (int j = 0; j < 8; j++)
            #pragma unroll
            for (int i = 0; i < 4; i++) sacc[j][i] = 0.f;

        #pragma unroll
        for (int p = 0; p < 4; p++) {          // n (l-col) pair: tiles 2p, 2p+1
            #pragma unroll
            for (int k = 0; k < 4; k++) {      // k (m) step
                // B-frag (non-trans from [n][k]=[l][m] storage):
                // m0: n lo/k lo -> b0 tile0; m1: n lo/k hi -> b1 tile0;
                // m2: n hi/k lo -> b0 tile1; m3: n hi/k hi -> b1 tile1
                const int nrow = p * 16 + (t4 >> 1) * 8 + r8;
                const int kc   = k * 16 + (t4 & 1) * 8;
                const uint32_t off = sw128(nrow * 128 + kc * 2);
                uint32_t bh[4], bl[4];
                ldmx4(sb + SKH + off, bh);
                ldmx4(sb + SKL + off, bl);
                mma16816(sacc[2*p],   qh[k], bh[0], bh[1]);
                mma16816(sacc[2*p+1], qh[k], bh[2], bh[3]);
                mma16816(sacc[2*p],   qh[k], bl[0], bl[1]);
                mma16816(sacc[2*p+1], qh[k], bl[2], bl[3]);
                mma16816(sacc[2*p],   ql[k], bh[0], bh[1]);
                mma16816(sacc[2*p+1], ql[k], bh[2], bh[3]);
            }
        }

        // ---- epilogue in registers: sigmoid, norm, split into GEMM2 A-frags ----
        // C-frag(tile j): c0,c1 = (row lo, col j*8+(lid%4)*2+{0,1}); c2,c3 = row hi.
        // A-frag(k-step kk): a0=pack(c0,c1) tile 2kk; a1=pack(c2,c3) tile 2kk;
        //                    a2=pack(c0,c1) tile 2kk+1; a3=pack(c2,c3) tile 2kk+1.
        uint32_t sh[4][4], sl[4][4];
        #pragma unroll
        for (int kk = 0; kk < 4; kk++) {
            float s0[4], s1[4];
            #pragma unroll
            for (int i = 0; i < 4; i++) {
                s0[i] = sigmoidf_fast(sacc[2*kk][i]);
                s1[i] = sigmoidf_fast(sacc[2*kk+1][i]);
            }
            normLo += (s0[0] + s0[1]) + (s1[0] + s1[1]);
            normHi += (s0[2] + s0[3]) + (s1[2] + s1[3]);
            split2(s0[0], s0[1], sh[kk][0], sl[kk][0]);
            split2(s0[2], s0[3], sh[kk][1], sl[kk][1]);
            split2(s1[0], s1[1], sh[kk][2], sl[kk][2]);
            split2(s1[2], s1[3], sh[kk][3], sl[kk][3]);
        }

        // ---- GEMM2: O[16x64] += S V, 3-way split (sh*vh + sh*vl + sl*vh) ----
        #pragma unroll
        for (int p = 0; p < 4; p++) {          // n (d-col) pair: tiles 2p, 2p+1
            #pragma unroll
            for (int kk = 0; kk < 4; kk++) {   // k (l) step
                // B-frag (.trans from [k][n]=[l][d] storage):
                // m0: l lo/d lo -> b0 tile0; m1: l hi/d lo -> b1 tile0;
                // m2: l lo/d hi -> b0 tile1; m3: l hi/d hi -> b1 tile1
                const int lrow = kk * 16 + (t4 & 1) * 8 + r8;
                const int dc   = p * 16 + (t4 >> 1) * 8;
                const uint32_t off = sw128(lrow * 128 + dc * 2);
                uint32_t vh[4], vl[4];
                ldmx4t(sb + SVH + off, vh);
                ldmx4t(sb + SVL + off, vl);
                mma16816(oacc[2*p],   sh[kk], vh[0], vh[1]);
                mma16816(oacc[2*p+1], sh[kk], vh[2], vh[3]);
                mma16816(oacc[2*p],   sh[kk], vl[0], vl[1]);
                mma16816(oacc[2*p+1], sh[kk], vl[2], vl[3]);
                mma16816(oacc[2*p],   sl[kk], vh[0], vh[1]);
                mma16816(oacc[2*p+1], sl[kk], vh[2], vh[3]);
            }
        }
        __syncthreads();   // protect K/V tiles before next iteration overwrites
    }

    // ---- finalize: quad-reduce norm (lanes lid&~3 share a row), scale, store ----
    #pragma unroll
    for (int m = 1; m <= 2; m <<= 1) {
        normLo += __shfl_xor_sync(0xffffffffu, normLo, m);
        normHi += __shfl_xor_sync(0xffffffffu, normHi, m);
    }
    const float invLo = 1.0f / normLo;
    const float invHi = 1.0f / normHi;

    const int rowLo = n0 + mw + (lid >> 2);
    const int rowHi = rowLo + 8;
    const int cbase = (lid & 3) * 2;
    #pragma unroll
    for (int j = 0; j < 8; j++) {
        float2 lo = make_float2(oacc[j][0] * invLo, oacc[j][1] * invLo);
        float2 hi = make_float2(oacc[j][2] * invHi, oacc[j][3] * invHi);
        *(float2*)(out + ((size_t)rowLo * HH + h) * DD + j * 8 + cbase) = lo;
        *(float2*)(out + ((size_t)rowHi * HH + h) * DD + j * 8 + cbase) = hi;
    }
}

extern "C" void kernel_launch(void* const* d_in, const int* in_sizes, int n_in,
                              void* d_out, int out_size)
{
    const float* queries = (const float*)d_in[0];
    const float* keys    = (const float*)d_in[1];
    const float* values  = (const float*)d_in[2];
    float* out = (float*)d_out;

    cudaFuncSetAttribute(diffattn_hmma,
                         cudaFuncAttributeMaxDynamicSharedMemorySize, SMEM_BYTES);

    const dim3 grid((NN / BM) * HH);   // 32 * 8 = 256 CTAs
    diffattn_hmma<<<grid, NTHREADS, SMEM_BYTES>>>(queries, keys, values, out);
}